// round 1
// baseline (speedup 1.0000x reference)
#include <cuda_runtime.h>
#include <cuda_bf16.h>
#include <cstdint>

// Problem dims (fixed by the reference setup_inputs)
#define I_DIM 4096   // K of the GEMM (input features)
#define O_DIM 4096   // N of the GEMM (output features)
#define R_DIM 4      // LoRA rank
#define M_DIM 8192   // B*S = 4*2048 rows of x

// Scratch: reconstructed effective weight, [O][I] row-major (K-contiguous).
// 64 MB static device array (allocation-free per harness rules).
__device__ float g_weight[(size_t)O_DIM * I_DIM];

// ---------------------------------------------------------------------------
// Kernel 1: fused weight reconstruction
//   w_int  = ori_round - zp[o]
//   lora   = (aux + (B@A)[o,i]) / (w_int==0 ? 1 : w_int)
//   wu     = delta[o] + lora
//   shift  = rint(log2(|wu| + 1e-16))          (round half-even, matches jnp.round)
//   weight = sign(wu) * exp2(shift) * w_int    (exp2 of integer is exact)
// ---------------------------------------------------------------------------
__global__ __launch_bounds__(256) void weight_reconstruct_kernel(
    const float* __restrict__ owr,     // [O, I]
    const float* __restrict__ delta,   // [O, 1]
    const float* __restrict__ zp,      // [O, 1]
    const float* __restrict__ aux,     // [O, I]
    const float* __restrict__ loraA,   // [R, I]
    const float* __restrict__ loraB)   // [O, R]
{
    const int o  = blockIdx.y;
    const int i0 = (blockIdx.x * 256 + threadIdx.x) * 4;

    const float d  = delta[o];
    const float z  = zp[o];
    const float b0 = loraB[o * R_DIM + 0];
    const float b1 = loraB[o * R_DIM + 1];
    const float b2 = loraB[o * R_DIM + 2];
    const float b3 = loraB[o * R_DIM + 3];

    const size_t base = (size_t)o * I_DIM + i0;
    const float4 w4 = *(const float4*)(owr + base);
    const float4 x4 = *(const float4*)(aux + base);
    const float4 a0 = *(const float4*)(loraA + 0 * I_DIM + i0);
    const float4 a1 = *(const float4*)(loraA + 1 * I_DIM + i0);
    const float4 a2 = *(const float4*)(loraA + 2 * I_DIM + i0);
    const float4 a3 = *(const float4*)(loraA + 3 * I_DIM + i0);

    const float wv[4]  = {w4.x, w4.y, w4.z, w4.w};
    const float av[4]  = {x4.x, x4.y, x4.z, x4.w};
    const float A0[4]  = {a0.x, a0.y, a0.z, a0.w};
    const float A1[4]  = {a1.x, a1.y, a1.z, a1.w};
    const float A2[4]  = {a2.x, a2.y, a2.z, a2.w};
    const float A3[4]  = {a3.x, a3.y, a3.z, a3.w};

    float out[4];
#pragma unroll
    for (int j = 0; j < 4; j++) {
        const float w_int = wv[j] - z;                       // exact (both integer-valued)
        const float denom = (w_int == 0.0f) ? 1.0f : w_int;
        // rank-4 dot, ascending r (matches BLAS small-k order)
        float ba = b0 * A0[j];
        ba = fmaf(b1, A1[j], ba);
        ba = fmaf(b2, A2[j], ba);
        ba = fmaf(b3, A3[j], ba);
        const float wu = d + (av[j] + ba) / denom;
        const float s  = (wu > 0.0f) ? 1.0f : ((wu < 0.0f) ? -1.0f : 0.0f);
        const float shift = rintf(log2f(fabsf(wu) + 1e-16f)); // half-even like jnp.round
        out[j] = s * exp2f(shift) * w_int;
    }
    *(float4*)(g_weight + base) = make_float4(out[0], out[1], out[2], out[3]);
}

// ---------------------------------------------------------------------------
// Kernel 2: SGEMM-NT  C[M,N] = A[M,K] * B[N,K]^T + bias[N]
//   A = x (row-major, K contiguous), B = g_weight (row-major, K contiguous)
//   128x128 block tile, K-tile 8, 256 threads, 8x8 register microtile.
// ---------------------------------------------------------------------------
#define BM 128
#define BN 128
#define BK 8
#define TM 8
#define TN 8

__global__ __launch_bounds__(256) void gemm_nt_kernel(
    const float* __restrict__ A,      // [M, K]
    const float* __restrict__ bias,   // [N]
    float* __restrict__ C)            // [M, N]
{
    __shared__ float As[BK][BM];
    __shared__ float Bs[BK][BN];

    const int tid = threadIdx.x;
    const int bm = blockIdx.y * BM;
    const int bn = blockIdx.x * BN;

    // loader mapping: 256 threads, each loads one float4 along K.
    // row = tid/2 in [0,128), kq = (tid&1)*4 in {0,4}
    const int lrow = tid >> 1;
    const int lkq  = (tid & 1) * 4;

    // compute mapping: 16x16 threads, each owns an 8x8 microtile
    const int ty = tid >> 4;   // 0..15 -> rows
    const int tx = tid & 15;   // 0..15 -> cols

    float acc[TM][TN];
#pragma unroll
    for (int i = 0; i < TM; i++)
#pragma unroll
        for (int j = 0; j < TN; j++) acc[i][j] = 0.0f;

    const float* Aptr = A + (size_t)(bm + lrow) * I_DIM + lkq;
    const float* Bptr = g_weight + (size_t)(bn + lrow) * I_DIM + lkq;

    for (int k0 = 0; k0 < I_DIM; k0 += BK) {
        const float4 av = *(const float4*)(Aptr + k0);
        const float4 bv = *(const float4*)(Bptr + k0);
        As[lkq + 0][lrow] = av.x;
        As[lkq + 1][lrow] = av.y;
        As[lkq + 2][lrow] = av.z;
        As[lkq + 3][lrow] = av.w;
        Bs[lkq + 0][lrow] = bv.x;
        Bs[lkq + 1][lrow] = bv.y;
        Bs[lkq + 2][lrow] = bv.z;
        Bs[lkq + 3][lrow] = bv.w;
        __syncthreads();

#pragma unroll
        for (int kk = 0; kk < BK; kk++) {
            float a[TM], b[TN];
#pragma unroll
            for (int i = 0; i < TM; i++) a[i] = As[kk][ty * TM + i];
#pragma unroll
            for (int j = 0; j < TN; j++) b[j] = Bs[kk][tx * TN + j];
#pragma unroll
            for (int i = 0; i < TM; i++)
#pragma unroll
                for (int j = 0; j < TN; j++)
                    acc[i][j] = fmaf(a[i], b[j], acc[i][j]);
        }
        __syncthreads();
    }

    // epilogue: bias add + vectorized store
    float bz[TN];
#pragma unroll
    for (int j = 0; j < TN; j++) bz[j] = bias[bn + tx * TN + j];

#pragma unroll
    for (int i = 0; i < TM; i++) {
        const int m = bm + ty * TM + i;
        float* crow = C + (size_t)m * O_DIM + bn + tx * TN;
        float4 v0 = make_float4(acc[i][0] + bz[0], acc[i][1] + bz[1],
                                acc[i][2] + bz[2], acc[i][3] + bz[3]);
        float4 v1 = make_float4(acc[i][4] + bz[4], acc[i][5] + bz[5],
                                acc[i][6] + bz[6], acc[i][7] + bz[7]);
        *(float4*)(crow + 0) = v0;
        *(float4*)(crow + 4) = v1;
    }
}

// ---------------------------------------------------------------------------
// Launch. Inputs (metadata order == reference signature order):
//   0: x [4,2048,4096]  1: ori_weight_round [O,I]  2: weight_quant_delta [O,1]
//   3: weight_quant_zero_point [O,1]  4: aux_R [O,I]  5: loraA_w [R,I]
//   6: loraB_w [O,R]  7: bias [O]
// Output: float32 [4,2048,4096]
// ---------------------------------------------------------------------------
extern "C" void kernel_launch(void* const* d_in, const int* in_sizes, int n_in,
                              void* d_out, int out_size)
{
    const float* x     = (const float*)d_in[0];
    const float* owr   = (const float*)d_in[1];
    const float* delta = (const float*)d_in[2];
    const float* zp    = (const float*)d_in[3];
    const float* aux   = (const float*)d_in[4];
    const float* loraA = (const float*)d_in[5];
    const float* loraB = (const float*)d_in[6];
    const float* bias  = (const float*)d_in[7];
    float* out = (float*)d_out;

    // Kernel 1: weight reconstruction  (I/1024 = 4 blocks in x, O blocks in y)
    dim3 g1(I_DIM / (256 * 4), O_DIM);
    weight_reconstruct_kernel<<<g1, 256>>>(owr, delta, zp, aux, loraA, loraB);

    // Kernel 2: GEMM  (N/128 = 32, M/128 = 64)
    dim3 g2(O_DIM / BN, M_DIM / BM);
    gemm_nt_kernel<<<g2, 256>>>(x, bias, out);
}

// round 4
// speedup vs baseline: 4.4778x; 4.4778x over previous
#include <cuda_runtime.h>
#include <cuda_bf16.h>
#include <cstdint>

// ---------------------------------------------------------------------------
// Problem dims
// ---------------------------------------------------------------------------
#define I_DIM 4096   // K
#define O_DIM 4096   // N
#define M_DIM 8192   // B*S
#define R_DIM 4

// GEMM tiling (Ampere-style mma.sync path: plain sm_100 has NO tcgen05)
#define BM 128
#define BN 128
#define BK 32
#define KITERS (I_DIM / BK)      // 128
#define STAGES 4

// SMEM stage layout: Ah[128][32]bf16 (8KB) | Al (8KB) | B[128][32]bf16 (8KB)
#define SA_HI 0
#define SA_LO 8192
#define SB    16384
#define STAGE_B 24576
#define SMEM_DYN (STAGES * STAGE_B)   // 98304 B

// ---------------------------------------------------------------------------
// Static scratch (allocation-free per harness rules)
// ---------------------------------------------------------------------------
__device__ __align__(256) __nv_bfloat16 g_x_hi[(size_t)M_DIM * I_DIM];
__device__ __align__(256) __nv_bfloat16 g_x_lo[(size_t)M_DIM * I_DIM];
__device__ __align__(256) __nv_bfloat16 g_wb  [(size_t)O_DIM * I_DIM];

// ---------------------------------------------------------------------------
// PTX helpers (sm_80-class only: cp.async, ldmatrix, mma.sync)
// ---------------------------------------------------------------------------
__device__ __forceinline__ uint32_t smem_u32(const void* p) {
    uint32_t a;
    asm("{ .reg .u64 t; cvta.to.shared.u64 t, %1; cvt.u32.u64 %0, t; }"
        : "=r"(a) : "l"(p));
    return a;
}

#define CP_A16(dst, src) \
    asm volatile("cp.async.cg.shared.global [%0], [%1], 16;" \
                 :: "r"(dst), "l"(src) : "memory")
#define CP_COMMIT() asm volatile("cp.async.commit_group;" ::: "memory")
#define CP_WAIT2()  asm volatile("cp.async.wait_group 2;" ::: "memory")

__device__ __forceinline__ void ldsm4(uint32_t (&r)[4], uint32_t addr) {
    asm volatile("ldmatrix.sync.aligned.m8n8.x4.shared.b16 {%0,%1,%2,%3}, [%4];"
                 : "=r"(r[0]), "=r"(r[1]), "=r"(r[2]), "=r"(r[3]) : "r"(addr));
}

__device__ __forceinline__ void mma16816(float* d, const uint32_t* a, const uint32_t* b) {
    asm volatile(
        "mma.sync.aligned.m16n8k16.row.col.f32.bf16.bf16.f32 "
        "{%0,%1,%2,%3}, {%4,%5,%6,%7}, {%8,%9}, {%0,%1,%2,%3};"
        : "+f"(d[0]), "+f"(d[1]), "+f"(d[2]), "+f"(d[3])
        : "r"(a[0]), "r"(a[1]), "r"(a[2]), "r"(a[3]), "r"(b[0]), "r"(b[1]));
}

// ---------------------------------------------------------------------------
// Kernel 1: x -> (x_hi, x_lo) bf16 split.  x_hi + x_lo ≈ x to ~2^-17 rel.
// ---------------------------------------------------------------------------
__global__ __launch_bounds__(256) void convert_x_kernel(const float* __restrict__ x) {
    const size_t i4 = ((size_t)blockIdx.x * 256 + threadIdx.x) * 4;
    const float4 v = *(const float4*)(x + i4);
    const float f[4] = {v.x, v.y, v.z, v.w};
    unsigned short h[4], l[4];
#pragma unroll
    for (int j = 0; j < 4; j++) {
        __nv_bfloat16 hb = __float2bfloat16_rn(f[j]);
        float r = f[j] - __bfloat162float(hb);
        __nv_bfloat16 lb = __float2bfloat16_rn(r);
        h[j] = __bfloat16_as_ushort(hb);
        l[j] = __bfloat16_as_ushort(lb);
    }
    uint2 hv, lv;
    hv.x = (uint32_t)h[0] | ((uint32_t)h[1] << 16);
    hv.y = (uint32_t)h[2] | ((uint32_t)h[3] << 16);
    lv.x = (uint32_t)l[0] | ((uint32_t)l[1] << 16);
    lv.y = (uint32_t)l[2] | ((uint32_t)l[3] << 16);
    *(uint2*)(g_x_hi + i4) = hv;
    *(uint2*)(g_x_lo + i4) = lv;
}

// ---------------------------------------------------------------------------
// Kernel 2: fused weight reconstruction -> bf16 (EXACT: |w_int| <= 255 fits
// bf16's 8 significand bits; 2^shift only moves the exponent).
// ---------------------------------------------------------------------------
__global__ __launch_bounds__(256) void weight_bf16_kernel(
    const float* __restrict__ owr, const float* __restrict__ delta,
    const float* __restrict__ zp,  const float* __restrict__ aux,
    const float* __restrict__ loraA, const float* __restrict__ loraB)
{
    const int o  = blockIdx.y;
    const int i0 = (blockIdx.x * 256 + threadIdx.x) * 4;

    const float d  = delta[o];
    const float z  = zp[o];
    const float b0 = loraB[o * R_DIM + 0];
    const float b1 = loraB[o * R_DIM + 1];
    const float b2 = loraB[o * R_DIM + 2];
    const float b3 = loraB[o * R_DIM + 3];

    const size_t base = (size_t)o * I_DIM + i0;
    const float4 w4 = *(const float4*)(owr + base);
    const float4 x4 = *(const float4*)(aux + base);
    const float4 a0 = *(const float4*)(loraA + 0 * I_DIM + i0);
    const float4 a1 = *(const float4*)(loraA + 1 * I_DIM + i0);
    const float4 a2 = *(const float4*)(loraA + 2 * I_DIM + i0);
    const float4 a3 = *(const float4*)(loraA + 3 * I_DIM + i0);

    const float wv[4] = {w4.x, w4.y, w4.z, w4.w};
    const float av[4] = {x4.x, x4.y, x4.z, x4.w};
    const float A0[4] = {a0.x, a0.y, a0.z, a0.w};
    const float A1[4] = {a1.x, a1.y, a1.z, a1.w};
    const float A2[4] = {a2.x, a2.y, a2.z, a2.w};
    const float A3[4] = {a3.x, a3.y, a3.z, a3.w};

    unsigned short out[4];
#pragma unroll
    for (int j = 0; j < 4; j++) {
        const float w_int = wv[j] - z;
        const float denom = (w_int == 0.0f) ? 1.0f : w_int;
        float ba = b0 * A0[j];
        ba = fmaf(b1, A1[j], ba);
        ba = fmaf(b2, A2[j], ba);
        ba = fmaf(b3, A3[j], ba);
        const float wu = d + (av[j] + ba) / denom;
        const float s  = (wu > 0.0f) ? 1.0f : ((wu < 0.0f) ? -1.0f : 0.0f);
        const float shift = rintf(log2f(fabsf(wu) + 1e-16f));
        const float w = s * exp2f(shift) * w_int;   // exactly bf16-representable
        out[j] = __bfloat16_as_ushort(__float2bfloat16_rn(w));
    }
    uint2 pv;
    pv.x = (uint32_t)out[0] | ((uint32_t)out[1] << 16);
    pv.y = (uint32_t)out[2] | ((uint32_t)out[3] << 16);
    *(uint2*)(g_wb + base) = pv;
}

// ---------------------------------------------------------------------------
// Kernel 3: mma.sync GEMM.  C = (x_hi + x_lo)[M,K] * W[N,K]^T + bias
//   128x128x32 CTA tile, 8 warps = 4(m) x 2(n), warp tile 32x64.
//   4-stage cp.async pipeline. W ([N,K], K-contig) IS col-major B for
//   mma.m16n8k16.row.col -> ldmatrix without .trans.
//   SMEM swizzle: chunk ^= (row>>1)&3  (conflict-free ldmatrix phases for
//   64-byte rows; the usual row&3 swizzle would 2-way conflict).
// ---------------------------------------------------------------------------
__global__ __launch_bounds__(256, 1) void gemm_mma_kernel(
    const float* __restrict__ bias, float* __restrict__ C)
{
    extern __shared__ char smem[];
    const uint32_t sbase = smem_u32(smem);
    const int tid  = threadIdx.x;
    const int lane = tid & 31;
    const int wid  = tid >> 5;
    const int warp_m = wid >> 1;                 // 0..3 (32 rows each)
    const int warp_n = wid & 1;                  // 0..1 (64 cols each)
    const int bm = blockIdx.y * BM;
    const int bn = blockIdx.x * BN;

    // ---- loader geometry: thread t loads chunk lc of row lr (+64) ----
    const int lr = tid >> 2;                     // 0..63
    const int lc = tid & 3;                      // 16B chunk in 64B row
    const uint32_t so0 = (uint32_t)(lr * 64 + ((lc ^ ((lr >> 1) & 3)) * 16));
    const char* gAh = (const char*)g_x_hi + (size_t)(bm + lr) * (I_DIM * 2) + lc * 16;
    const char* gAl = (const char*)g_x_lo + (size_t)(bm + lr) * (I_DIM * 2) + lc * 16;
    const char* gB  = (const char*)g_wb  + (size_t)(bn + lr) * (I_DIM * 2) + lc * 16;
    const size_t RSTEP = (size_t)64 * (I_DIM * 2);

    auto load_stage = [&](int s, int kt) {
        const uint32_t st = sbase + s * STAGE_B;
        const size_t ko = (size_t)kt * (BK * 2);
        CP_A16(st + SA_HI + so0,        gAh + ko);
        CP_A16(st + SA_HI + so0 + 4096, gAh + ko + RSTEP);
        CP_A16(st + SA_LO + so0,        gAl + ko);
        CP_A16(st + SA_LO + so0 + 4096, gAl + ko + RSTEP);
        CP_A16(st + SB    + so0,        gB  + ko);
        CP_A16(st + SB    + so0 + 4096, gB  + ko + RSTEP);
    };

    // ---- ldmatrix lane offsets for ks=0; XOR 32 flips to ks=1 chunk pair ----
    uint32_t aoff[2], boff[4];
    {
        const int ar  = warp_m * 32 + (lane & 15);
        const int ach = lane >> 4;                       // 0/1 = k-chunk bit
#pragma unroll
        for (int i = 0; i < 2; ++i) {
            const int r = ar + i * 16;
            aoff[i] = (uint32_t)(r * 64 + ((ach ^ ((r >> 1) & 3)) * 16));
        }
        const int br  = warp_n * 64 + ((lane >> 4) << 3) + (lane & 7);
        const int bch = (lane >> 3) & 1;
#pragma unroll
        for (int j = 0; j < 4; ++j) {
            const int r = br + j * 16;
            boff[j] = (uint32_t)(r * 64 + ((bch ^ ((r >> 1) & 3)) * 16));
        }
    }

    float acc[2][8][4];
#pragma unroll
    for (int i = 0; i < 2; ++i)
#pragma unroll
        for (int j = 0; j < 8; ++j)
#pragma unroll
            for (int c = 0; c < 4; ++c) acc[i][j][c] = 0.0f;

    // ---- prologue: fill 3 stages ----
    load_stage(0, 0); CP_COMMIT();
    load_stage(1, 1); CP_COMMIT();
    load_stage(2, 2); CP_COMMIT();

    for (int kt = 0; kt < KITERS; ++kt) {
        CP_WAIT2();                  // group kt complete (groups retire in order)
        __syncthreads();             // all warps done reading stage (kt-1)&3
        if (kt + 3 < KITERS) load_stage((kt + 3) & 3, kt + 3);
        CP_COMMIT();                 // empty group near the tail keeps indexing uniform

        const uint32_t st = sbase + (kt & 3) * STAGE_B;
#pragma unroll
        for (int ks = 0; ks < 2; ++ks) {
            const uint32_t kx = ks * 32;
            uint32_t ah[2][4], al[2][4], bf[4][4];
#pragma unroll
            for (int i = 0; i < 2; ++i) {
                ldsm4(ah[i], st + SA_HI + (aoff[i] ^ kx));
                ldsm4(al[i], st + SA_LO + (aoff[i] ^ kx));
            }
#pragma unroll
            for (int j = 0; j < 4; ++j)
                ldsm4(bf[j], st + SB + (boff[j] ^ kx));
            // bf[j] = { b(n=16j+0..7, k0-7), b(.., k8-15), b(n+8, k0-7), b(n+8, k8-15) }
#pragma unroll
            for (int i = 0; i < 2; ++i)
#pragma unroll
                for (int j = 0; j < 4; ++j) {
                    mma16816(acc[i][2 * j],     ah[i], &bf[j][0]);
                    mma16816(acc[i][2 * j + 1], ah[i], &bf[j][2]);
                    mma16816(acc[i][2 * j],     al[i], &bf[j][0]);
                    mma16816(acc[i][2 * j + 1], al[i], &bf[j][2]);
                }
        }
    }

    // ---- epilogue: d-frag rows lane>>2 (+8), cols (lane&3)*2 ----
#pragma unroll
    for (int i = 0; i < 2; ++i) {
        const int r0 = bm + warp_m * 32 + i * 16 + (lane >> 2);
#pragma unroll
        for (int jn = 0; jn < 8; ++jn) {
            const int col = bn + warp_n * 64 + jn * 8 + (lane & 3) * 2;
            const float2 bz = *(const float2*)(bias + col);
            float2 v0 = make_float2(acc[i][jn][0] + bz.x, acc[i][jn][1] + bz.y);
            float2 v1 = make_float2(acc[i][jn][2] + bz.x, acc[i][jn][3] + bz.y);
            *(float2*)(C + (size_t)r0 * O_DIM + col)       = v0;
            *(float2*)(C + (size_t)(r0 + 8) * O_DIM + col) = v1;
        }
    }
}

// ---------------------------------------------------------------------------
// Launch
// ---------------------------------------------------------------------------
extern "C" void kernel_launch(void* const* d_in, const int* in_sizes, int n_in,
                              void* d_out, int out_size)
{
    const float* x     = (const float*)d_in[0];
    const float* owr   = (const float*)d_in[1];
    const float* delta = (const float*)d_in[2];
    const float* zp    = (const float*)d_in[3];
    const float* aux   = (const float*)d_in[4];
    const float* loraA = (const float*)d_in[5];
    const float* loraB = (const float*)d_in[6];
    const float* bias  = (const float*)d_in[7];
    float* out = (float*)d_out;

    cudaFuncSetAttribute(gemm_mma_kernel,
                         cudaFuncAttributeMaxDynamicSharedMemorySize, SMEM_DYN);

    // 1) x -> bf16 hi/lo split
    convert_x_kernel<<<(int)(((size_t)M_DIM * I_DIM) / (256 * 4)), 256>>>(x);

    // 2) weight reconstruction -> bf16
    weight_bf16_kernel<<<dim3(I_DIM / 1024, O_DIM), 256>>>(owr, delta, zp, aux, loraA, loraB);

    // 3) tensor-core GEMM (mma.sync) + bias
    gemm_mma_kernel<<<dim3(O_DIM / BN, M_DIM / BM), 256, SMEM_DYN>>>(bias, out);
}

// round 6
// speedup vs baseline: 9.3630x; 2.0910x over previous
#include <cuda_runtime.h>
#include <cuda_fp16.h>
#include <cstdint>

// ---------------------------------------------------------------------------
// Problem dims
// ---------------------------------------------------------------------------
#define I_DIM 4096   // K
#define O_DIM 4096   // N
#define M_DIM 8192   // B*S
#define R_DIM 4

// GEMM tiling (Ampere-style mma.sync path: plain sm_100 target, no tcgen05)
#define BM 128
#define BN 128
#define BK 32
#define KITERS (I_DIM / BK)      // 128
#define STAGES 4

// SMEM stage layout: A[128][32]fp16 (8KB) | B[128][32]fp16 (8KB)
#define SA 0
#define SB 8192
#define STAGE_B 16384
#define SMEM_DYN (STAGES * STAGE_B)   // 65536 B  -> 2 CTAs/SM fit

// ---------------------------------------------------------------------------
// Static scratch (allocation-free per harness rules)
// ---------------------------------------------------------------------------
__device__ __align__(256) __half g_x16[(size_t)M_DIM * I_DIM];   // 64 MB
__device__ __align__(256) __half g_w16[(size_t)O_DIM * I_DIM];   // 32 MB

// ---------------------------------------------------------------------------
// PTX helpers (sm_80-class: cp.async, ldmatrix, mma.sync)
// ---------------------------------------------------------------------------
__device__ __forceinline__ uint32_t smem_u32(const void* p) {
    uint32_t a;
    asm("{ .reg .u64 t; cvta.to.shared.u64 t, %1; cvt.u32.u64 %0, t; }"
        : "=r"(a) : "l"(p));
    return a;
}

#define CP_A16(dst, src) \
    asm volatile("cp.async.cg.shared.global [%0], [%1], 16;" \
                 :: "r"(dst), "l"(src) : "memory")
#define CP_COMMIT() asm volatile("cp.async.commit_group;" ::: "memory")
#define CP_WAIT2()  asm volatile("cp.async.wait_group 2;" ::: "memory")

__device__ __forceinline__ void ldsm4(uint32_t (&r)[4], uint32_t addr) {
    asm volatile("ldmatrix.sync.aligned.m8n8.x4.shared.b16 {%0,%1,%2,%3}, [%4];"
                 : "=r"(r[0]), "=r"(r[1]), "=r"(r[2]), "=r"(r[3]) : "r"(addr));
}

__device__ __forceinline__ void mma16816(float* d, const uint32_t* a, const uint32_t* b) {
    asm volatile(
        "mma.sync.aligned.m16n8k16.row.col.f32.f16.f16.f32 "
        "{%0,%1,%2,%3}, {%4,%5,%6,%7}, {%8,%9}, {%0,%1,%2,%3};"
        : "+f"(d[0]), "+f"(d[1]), "+f"(d[2]), "+f"(d[3])
        : "r"(a[0]), "r"(a[1]), "r"(a[2]), "r"(a[3]), "r"(b[0]), "r"(b[1]));
}

// ---------------------------------------------------------------------------
// Kernel 1: x -> fp16 (single buffer; rel rounding ~2^-11, output-safe:
// the fp16 x-rounding contributes ~1.4e-4 rel err at the output, and the
// shift-rounding term already present contributes ~1.1e-4; sum << 1e-3).
// ---------------------------------------------------------------------------
__global__ __launch_bounds__(256) void convert_x_kernel(const float* __restrict__ x) {
    const size_t i4 = ((size_t)blockIdx.x * 256 + threadIdx.x) * 4;
    const float4 v = *(const float4*)(x + i4);
    unsigned short h[4];
    h[0] = __half_as_ushort(__float2half_rn(v.x));
    h[1] = __half_as_ushort(__float2half_rn(v.y));
    h[2] = __half_as_ushort(__float2half_rn(v.z));
    h[3] = __half_as_ushort(__float2half_rn(v.w));
    uint2 hv;
    hv.x = (uint32_t)h[0] | ((uint32_t)h[1] << 16);
    hv.y = (uint32_t)h[2] | ((uint32_t)h[3] << 16);
    *(uint2*)(g_x16 + i4) = hv;
}

// ---------------------------------------------------------------------------
// Kernel 2: fused weight reconstruction -> fp16.
// w = sign * 2^shift * w_int, |w_int| <= 255 (8 bits) < fp16's 11 mantissa
// bits, shift in ~[-13,-3] -> representation is EXACT.
// ---------------------------------------------------------------------------
__global__ __launch_bounds__(256) void weight_f16_kernel(
    const float* __restrict__ owr, const float* __restrict__ delta,
    const float* __restrict__ zp,  const float* __restrict__ aux,
    const float* __restrict__ loraA, const float* __restrict__ loraB)
{
    const int o  = blockIdx.y;
    const int i0 = (blockIdx.x * 256 + threadIdx.x) * 4;

    const float d  = delta[o];
    const float z  = zp[o];
    const float b0 = loraB[o * R_DIM + 0];
    const float b1 = loraB[o * R_DIM + 1];
    const float b2 = loraB[o * R_DIM + 2];
    const float b3 = loraB[o * R_DIM + 3];

    const size_t base = (size_t)o * I_DIM + i0;
    const float4 w4 = *(const float4*)(owr + base);
    const float4 x4 = *(const float4*)(aux + base);
    const float4 a0 = *(const float4*)(loraA + 0 * I_DIM + i0);
    const float4 a1 = *(const float4*)(loraA + 1 * I_DIM + i0);
    const float4 a2 = *(const float4*)(loraA + 2 * I_DIM + i0);
    const float4 a3 = *(const float4*)(loraA + 3 * I_DIM + i0);

    const float wv[4] = {w4.x, w4.y, w4.z, w4.w};
    const float av[4] = {x4.x, x4.y, x4.z, x4.w};
    const float A0[4] = {a0.x, a0.y, a0.z, a0.w};
    const float A1[4] = {a1.x, a1.y, a1.z, a1.w};
    const float A2[4] = {a2.x, a2.y, a2.z, a2.w};
    const float A3[4] = {a3.x, a3.y, a3.z, a3.w};

    unsigned short out[4];
#pragma unroll
    for (int j = 0; j < 4; j++) {
        const float w_int = wv[j] - z;
        const float denom = (w_int == 0.0f) ? 1.0f : w_int;
        float ba = b0 * A0[j];
        ba = fmaf(b1, A1[j], ba);
        ba = fmaf(b2, A2[j], ba);
        ba = fmaf(b3, A3[j], ba);
        const float wu = d + (av[j] + ba) / denom;
        const float s  = (wu > 0.0f) ? 1.0f : ((wu < 0.0f) ? -1.0f : 0.0f);
        const float shift = rintf(log2f(fabsf(wu) + 1e-16f));
        const float w = s * exp2f(shift) * w_int;   // exactly fp16-representable
        out[j] = __half_as_ushort(__float2half_rn(w));
    }
    uint2 pv;
    pv.x = (uint32_t)out[0] | ((uint32_t)out[1] << 16);
    pv.y = (uint32_t)out[2] | ((uint32_t)out[3] << 16);
    *(uint2*)(g_w16 + base) = pv;
}

// ---------------------------------------------------------------------------
// Kernel 3: mma.sync fp16 GEMM.  C = x16[M,K] * W16[N,K]^T + bias
//   128x128x32 CTA tile, 8 warps = 4(m) x 2(n), warp tile 32x64.
//   4-stage cp.async pipeline, 2 CTAs/SM.
//   W ([N,K], K-contig) IS col-major B for mma.row.col -> ldmatrix no .trans.
//   SMEM swizzle: chunk ^= (row>>1)&3 (conflict-free ldmatrix phases, 64B rows).
// ---------------------------------------------------------------------------
__global__ __launch_bounds__(256, 2) void gemm_mma_kernel(
    const float* __restrict__ bias, float* __restrict__ C)
{
    extern __shared__ char smem[];
    const uint32_t sbase = smem_u32(smem);
    const int tid  = threadIdx.x;
    const int lane = tid & 31;
    const int wid  = tid >> 5;
    const int warp_m = wid >> 1;                 // 0..3 (32 rows each)
    const int warp_n = wid & 1;                  // 0..1 (64 cols each)
    const int bm = blockIdx.y * BM;
    const int bn = blockIdx.x * BN;

    // ---- loader geometry: thread t loads chunk lc of rows lr and lr+64 ----
    const int lr = tid >> 2;                     // 0..63
    const int lc = tid & 3;                      // 16B chunk within 64B row
    const uint32_t so0 = (uint32_t)(lr * 64 + ((lc ^ ((lr >> 1) & 3)) * 16));
    const char* gA = (const char*)g_x16 + (size_t)(bm + lr) * (I_DIM * 2) + lc * 16;
    const char* gB = (const char*)g_w16 + (size_t)(bn + lr) * (I_DIM * 2) + lc * 16;
    const size_t RSTEP = (size_t)64 * (I_DIM * 2);

    auto load_stage = [&](int s, int kt) {
        const uint32_t st = sbase + s * STAGE_B;
        const size_t ko = (size_t)kt * (BK * 2);
        CP_A16(st + SA + so0,        gA + ko);
        CP_A16(st + SA + so0 + 4096, gA + ko + RSTEP);
        CP_A16(st + SB + so0,        gB + ko);
        CP_A16(st + SB + so0 + 4096, gB + ko + RSTEP);
    };

    // ---- ldmatrix lane offsets for ks=0; XOR 32 flips to the ks=1 chunks ----
    uint32_t aoff[2], boff[4];
    {
        const int ar  = warp_m * 32 + (lane & 15);
        const int ach = lane >> 4;                       // k-chunk bit
#pragma unroll
        for (int i = 0; i < 2; ++i) {
            const int r = ar + i * 16;
            aoff[i] = (uint32_t)(r * 64 + ((ach ^ ((r >> 1) & 3)) * 16));
        }
        const int br  = warp_n * 64 + ((lane >> 4) << 3) + (lane & 7);
        const int bch = (lane >> 3) & 1;
#pragma unroll
        for (int j = 0; j < 4; ++j) {
            const int r = br + j * 16;
            boff[j] = (uint32_t)(r * 64 + ((bch ^ ((r >> 1) & 3)) * 16));
        }
    }

    float acc[2][8][4];
#pragma unroll
    for (int i = 0; i < 2; ++i)
#pragma unroll
        for (int j = 0; j < 8; ++j)
#pragma unroll
            for (int c = 0; c < 4; ++c) acc[i][j][c] = 0.0f;

    // ---- prologue: fill 3 stages ----
    load_stage(0, 0); CP_COMMIT();
    load_stage(1, 1); CP_COMMIT();
    load_stage(2, 2); CP_COMMIT();

    for (int kt = 0; kt < KITERS; ++kt) {
        CP_WAIT2();                  // stage kt resident (groups retire in order)
        __syncthreads();             // all warps done reading stage (kt-1)&3
        if (kt + 3 < KITERS) load_stage((kt + 3) & 3, kt + 3);
        CP_COMMIT();                 // empty tail groups keep wait index uniform

        const uint32_t st = sbase + (kt & 3) * STAGE_B;
#pragma unroll
        for (int ks = 0; ks < 2; ++ks) {
            const uint32_t kx = ks * 32;
            uint32_t af[2][4], bf[4][4];
#pragma unroll
            for (int i = 0; i < 2; ++i)
                ldsm4(af[i], st + SA + (aoff[i] ^ kx));
#pragma unroll
            for (int j = 0; j < 4; ++j)
                ldsm4(bf[j], st + SB + (boff[j] ^ kx));
            // bf[j] = { b(n=16j+0..7,k0-7), b(..,k8-15), b(n+8,k0-7), b(n+8,k8-15) }
#pragma unroll
            for (int i = 0; i < 2; ++i)
#pragma unroll
                for (int j = 0; j < 4; ++j) {
                    mma16816(acc[i][2 * j],     af[i], &bf[j][0]);
                    mma16816(acc[i][2 * j + 1], af[i], &bf[j][2]);
                }
        }
    }

    // ---- epilogue: d-frag rows lane>>2 (+8), cols (lane&3)*2 ----
#pragma unroll
    for (int i = 0; i < 2; ++i) {
        const int r0 = bm + warp_m * 32 + i * 16 + (lane >> 2);
#pragma unroll
        for (int jn = 0; jn < 8; ++jn) {
            const int col = bn + warp_n * 64 + jn * 8 + (lane & 3) * 2;
            const float2 bz = *(const float2*)(bias + col);
            float2 v0 = make_float2(acc[i][jn][0] + bz.x, acc[i][jn][1] + bz.y);
            float2 v1 = make_float2(acc[i][jn][2] + bz.x, acc[i][jn][3] + bz.y);
            *(float2*)(C + (size_t)r0 * O_DIM + col)       = v0;
            *(float2*)(C + (size_t)(r0 + 8) * O_DIM + col) = v1;
        }
    }
}

// ---------------------------------------------------------------------------
// Launch
// ---------------------------------------------------------------------------
extern "C" void kernel_launch(void* const* d_in, const int* in_sizes, int n_in,
                              void* d_out, int out_size)
{
    const float* x     = (const float*)d_in[0];
    const float* owr   = (const float*)d_in[1];
    const float* delta = (const float*)d_in[2];
    const float* zp    = (const float*)d_in[3];
    const float* aux   = (const float*)d_in[4];
    const float* loraA = (const float*)d_in[5];
    const float* loraB = (const float*)d_in[6];
    const float* bias  = (const float*)d_in[7];
    float* out = (float*)d_out;

    cudaFuncSetAttribute(gemm_mma_kernel,
                         cudaFuncAttributeMaxDynamicSharedMemorySize, SMEM_DYN);

    // 1) x -> fp16
    convert_x_kernel<<<(int)(((size_t)M_DIM * I_DIM) / (256 * 4)), 256>>>(x);

    // 2) weight reconstruction -> fp16 (exact representation)
    weight_f16_kernel<<<dim3(I_DIM / 1024, O_DIM), 256>>>(owr, delta, zp, aux, loraA, loraB);

    // 3) tensor-core GEMM (fp16 mma.sync, fp32 accum) + bias
    gemm_mma_kernel<<<dim3(O_DIM / BN, M_DIM / BM), 256, SMEM_DYN>>>(bias, out);
}